// round 4
// baseline (speedup 1.0000x reference)
#include <cuda_runtime.h>
#include <math.h>

#define NN 1024
#define NPG 128
#define NB 8
#define KM 64
#define H 600
#define G 50
#define NL 6
#define NC 259           // coarse knots, d=(q-1)*D0, q=0..258
#define D0 (10.0f/256.0f)

__device__ float g_h[NN*H], g_x1[NN*H], g_msg[NN*H], g_m1[NN*H];
__device__ float g_T[NL*NC*H], g_tmp[NC*H], g_ea[NC*G], g_C[NC];
__device__ float g_pool[NB*H];
__device__ int   g_nbr[NN*KM], g_base[NN*KM], g_cnt[NN];
__device__ float g_w4[NN*KM*4];

__device__ __forceinline__ float sspf(float x){
    float r = (x > 0.f) ? (x + log1pf(expf(-x))) : log1pf(expf(x));
    return r - 0.69314718055994530942f;
}

// ---- graph build: 1 block per node, matches jax top_k(-dist2, K) ----
__global__ void build_graph(const float* __restrict__ pos){
    int i = blockIdx.x, b = i/NPG, il = i - b*NPG, j = threadIdx.x;
    __shared__ float sx[NPG], sy[NPG], sz[NPG], sd2[NPG];
    __shared__ int scnt;
    const float* pg = pos + (size_t)b*NPG*3;
    sx[j]=pg[j*3]; sy[j]=pg[j*3+1]; sz[j]=pg[j*3+2];
    if(j==0) scnt=0;
    __syncthreads();
    float dx=__fsub_rn(sx[il],sx[j]), dy=__fsub_rn(sy[il],sy[j]), dz=__fsub_rn(sz[il],sz[j]);
    float d2=__fadd_rn(__fadd_rn(__fmul_rn(dx,dx),__fmul_rn(dy,dy)),__fmul_rn(dz,dz));
    bool ok = (d2<=100.0f) && (j!=il);
    sd2[j] = ok ? d2 : 3.0e38f;
    __syncthreads();
    int rank=0;
    if(ok){
        #pragma unroll 8
        for(int t=0;t<NPG;t++){ float o=sd2[t]; rank += (o<d2)||(o==d2 && t<j); }
        atomicAdd(&scnt,1);
    }
    __syncthreads();
    if(j==0) g_cnt[i] = min(scnt,KM);
    if(ok && rank<KM){
        float d = sqrtf(d2);
        float u = d * (1.0f/D0);
        int s = (int)u; if(s>255) s=255; if(s<0) s=0;
        float t = u - (float)s;
        float t2=t*t, t3=t2*t;
        int e=i*KM+rank;
        g_nbr[e]=b*NPG+j; g_base[e]=s*H;
        g_w4[e*4+0]=0.5f*(-t3+2.f*t2-t);
        g_w4[e*4+1]=0.5f*(3.f*t3-5.f*t2+2.f);
        g_w4[e*4+2]=0.5f*(-3.f*t3+4.f*t2+t);
        g_w4[e*4+3]=0.5f*(t3-t2);
    }
}

// ---- gaussian smearing + cosine cutoff on coarse grid ----
__global__ void smear(){
    int idx = blockIdx.x*blockDim.x + threadIdx.x;
    if(idx >= NC*G) return;
    int q = idx/G, g = idx - q*G;
    float d = (float)(q-1)*D0;
    float step = 10.0f/49.0f;
    float x = d - (float)g*step;
    g_ea[idx] = expf((-0.5f/(step*step))*x*x);
    if(g==0) g_C[q] = 0.5f*(cosf(d*0.31415926535897932f)+1.0f);
}

__global__ void embed(const float* __restrict__ emb, const int* __restrict__ z){
    int idx = blockIdx.x*blockDim.x + threadIdx.x;
    if(idx >= NN*H) return;
    int i = idx/H;
    g_h[idx] = emb[z[i]*H + (idx - i*H)];
}

// ---- aggregation: msg_i[h] = sum_k cubic(T_l, d_ik)[h] * x1[nbr][h] ----
__global__ void __launch_bounds__(640) agg(int l){
    int i = blockIdx.x, t = threadIdx.x;
    __shared__ int s_j[KM], s_b[KM], s_cnt;
    __shared__ float s_w[KM*4];
    if(t==0) s_cnt = g_cnt[i];
    if(t<KM){
        int e=i*KM+t;
        s_j[t]=g_nbr[e]*H; s_b[t]=g_base[e];
        s_w[t*4]=g_w4[e*4]; s_w[t*4+1]=g_w4[e*4+1];
        s_w[t*4+2]=g_w4[e*4+2]; s_w[t*4+3]=g_w4[e*4+3];
    }
    __syncthreads();
    if(t >= H) return;
    const float* T = g_T + (size_t)l*NC*H + t;
    int cnt = s_cnt;
    float acc = 0.f;
    #pragma unroll 2
    for(int k=0;k<cnt;k++){
        const float* tp = T + s_b[k];
        float v = s_w[k*4]*__ldg(tp) + s_w[k*4+1]*__ldg(tp+H)
                + s_w[k*4+2]*__ldg(tp+2*H) + s_w[k*4+3]*__ldg(tp+3*H);
        acc = fmaf(v, __ldg(&g_x1[s_j[k]+t]), acc);
    }
    g_msg[i*H+t] = acc;
}

// ---- SIMT fp32 GEMM, C = epi(A[M,K]@B[K,N] + bias) ----
// EPI: 0 plain, 1 ssp, 2 +=extra[m*N+n], 3 *=extra[m]
template<int EPI>
__global__ void __launch_bounds__(256) sgemm(const float* __restrict__ A,
        const float* __restrict__ B, const float* bias, const float* extra,
        float* Cm, int M, int N, int K){
    const int BM=64, BN=64, BK=16;
    __shared__ float As[BK][BM], Bs[BK][BN];
    int tid=threadIdx.x, tx=tid&15, ty=tid>>4;
    int m0=blockIdx.y*BM, n0=blockIdx.x*BN;
    int ar=tid>>2, ac=(tid&3)<<2, br=tid>>4, bc=(tid&15)<<2;
    float acc[4][4];
    #pragma unroll
    for(int a=0;a<4;a++)
        #pragma unroll
        for(int c=0;c<4;c++) acc[a][c]=0.f;
    for(int k0=0;k0<K;k0+=BK){
        int gm=m0+ar;
        #pragma unroll
        for(int u=0;u<4;u++){
            int gk=k0+ac+u;
            As[ac+u][ar] = (gm<M && gk<K) ? A[(size_t)gm*K+gk] : 0.f;
        }
        int gk2=k0+br;
        #pragma unroll
        for(int u=0;u<4;u++){
            int gn=n0+bc+u;
            Bs[br][bc+u] = (gk2<K && gn<N) ? B[(size_t)gk2*N+gn] : 0.f;
        }
        __syncthreads();
        #pragma unroll
        for(int kk=0;kk<BK;kk++){
            float4 av=*reinterpret_cast<const float4*>(&As[kk][ty<<2]);
            float4 bv=*reinterpret_cast<const float4*>(&Bs[kk][tx<<2]);
            float a0=av.x,a1=av.y,a2=av.z,a3=av.w;
            float b0=bv.x,b1=bv.y,b2=bv.z,b3=bv.w;
            acc[0][0]=fmaf(a0,b0,acc[0][0]); acc[0][1]=fmaf(a0,b1,acc[0][1]);
            acc[0][2]=fmaf(a0,b2,acc[0][2]); acc[0][3]=fmaf(a0,b3,acc[0][3]);
            acc[1][0]=fmaf(a1,b0,acc[1][0]); acc[1][1]=fmaf(a1,b1,acc[1][1]);
            acc[1][2]=fmaf(a1,b2,acc[1][2]); acc[1][3]=fmaf(a1,b3,acc[1][3]);
            acc[2][0]=fmaf(a2,b0,acc[2][0]); acc[2][1]=fmaf(a2,b1,acc[2][1]);
            acc[2][2]=fmaf(a2,b2,acc[2][2]); acc[2][3]=fmaf(a2,b3,acc[2][3]);
            acc[3][0]=fmaf(a3,b0,acc[3][0]); acc[3][1]=fmaf(a3,b1,acc[3][1]);
            acc[3][2]=fmaf(a3,b2,acc[3][2]); acc[3][3]=fmaf(a3,b3,acc[3][3]);
        }
        __syncthreads();
    }
    #pragma unroll
    for(int ii=0;ii<4;ii++){
        int m=m0+(ty<<2)+ii;
        if(m>=M) continue;
        #pragma unroll
        for(int jj=0;jj<4;jj++){
            int n=n0+(tx<<2)+jj;
            if(n>=N) continue;
            float v=acc[ii][jj];
            if(bias) v += bias[n];
            if(EPI==1) v = sspf(v);
            else if(EPI==2) v += extra[(size_t)m*N+n];
            else if(EPI==3) v *= extra[m];
            Cm[(size_t)m*N+n]=v;
        }
    }
}

__global__ void pool(){
    int idx = blockIdx.x*blockDim.x + threadIdx.x;
    if(idx >= NB*H) return;
    int b = idx/H, h = idx - b*H;
    const float* p = g_h + (size_t)b*NPG*H + h;
    float s = 0.f;
    #pragma unroll 8
    for(int n=0;n<NPG;n++) s += p[(size_t)n*H];
    g_pool[idx] = s * (1.0f/NPG);
}

__global__ void final_lin(const float* __restrict__ pw, const float* __restrict__ pb,
                          float* __restrict__ out){
    int idx = blockIdx.x*blockDim.x + threadIdx.x;
    if(idx >= NB*H) return;
    int b = idx/H, n = idx - b*H;
    const float* pr = g_pool + b*H;
    float s = pb[n];
    for(int k=0;k<H;k++) s = fmaf(pr[k], pw[(size_t)k*H+n], s);
    out[idx] = s;
}

extern "C" void kernel_launch(void* const* d_in, const int* in_sizes, int n_in,
                              void* d_out, int out_size){
    // dict order: z,pos,emb,w1,b1,w2,b2,lin1,l2w,l2b,ilw,ilb,pw,pb
    int map[14] = {0,1,2,3,4,5,6,7,8,9,10,11,12,13};
    if(!(in_sizes[0]==1024 && in_sizes[1]==3072)){
        // signature order: pos,...,z
        int sig[14] = {13,0,1,2,3,4,5,6,7,8,9,10,11,12};
        for(int i=0;i<14;i++) map[i]=sig[i];
    }
    const int*   z    = (const int*)  d_in[map[0]];
    const float* posv = (const float*)d_in[map[1]];
    const float* emb  = (const float*)d_in[map[2]];
    const float* w1   = (const float*)d_in[map[3]];
    const float* b1   = (const float*)d_in[map[4]];
    const float* w2   = (const float*)d_in[map[5]];
    const float* b2   = (const float*)d_in[map[6]];
    const float* lin1 = (const float*)d_in[map[7]];
    const float* l2w  = (const float*)d_in[map[8]];
    const float* l2b  = (const float*)d_in[map[9]];
    const float* ilw  = (const float*)d_in[map[10]];
    const float* ilb  = (const float*)d_in[map[11]];
    const float* pw   = (const float*)d_in[map[12]];
    const float* pb   = (const float*)d_in[map[13]];
    float* out = (float*)d_out;

    float *p_h,*p_x1,*p_msg,*p_m1,*p_T,*p_tmp,*p_ea,*p_C;
    cudaGetSymbolAddress((void**)&p_h,  g_h);
    cudaGetSymbolAddress((void**)&p_x1, g_x1);
    cudaGetSymbolAddress((void**)&p_msg,g_msg);
    cudaGetSymbolAddress((void**)&p_m1, g_m1);
    cudaGetSymbolAddress((void**)&p_T,  g_T);
    cudaGetSymbolAddress((void**)&p_tmp,g_tmp);
    cudaGetSymbolAddress((void**)&p_ea, g_ea);
    cudaGetSymbolAddress((void**)&p_C,  g_C);

    dim3 gN((H+63)/64, (NN+63)/64);   // node GEMMs: 10 x 16
    dim3 gC((H+63)/64, (NC+63)/64);   // table GEMMs: 10 x 5

    build_graph<<<NN, NPG>>>(posv);
    smear<<<(NC*G+255)/256, 256>>>();
    embed<<<(NN*H+255)/256, 256>>>(emb, z);

    for(int l=0;l<NL;l++){
        // coarse filter table for layer l
        sgemm<1><<<gC,256>>>(p_ea, w1+(size_t)l*G*H, b1+l*H, nullptr, p_tmp, NC, H, G);
        sgemm<3><<<gC,256>>>(p_tmp, w2+(size_t)l*H*H, b2+l*H, p_C, p_T+(size_t)l*NC*H, NC, H, H);
        // x1 = h @ lin1 (no bias)
        sgemm<0><<<gN,256>>>(p_h, lin1+(size_t)l*H*H, nullptr, nullptr, p_x1, NN, H, H);
        agg<<<NN, 640>>>(l);
        sgemm<1><<<gN,256>>>(p_msg, l2w+(size_t)l*H*H, l2b+l*H, nullptr, p_m1, NN, H, H);
        sgemm<2><<<gN,256>>>(p_m1, ilw+(size_t)l*H*H, ilb+l*H, p_h, p_h, NN, H, H);
    }
    pool<<<(NB*H+255)/256, 256>>>();
    final_lin<<<(NB*H+255)/256, 256>>>(pw, pb, out);
}

// round 5
// speedup vs baseline: 1.6628x; 1.6628x over previous
#include <cuda_runtime.h>
#include <math.h>

#define NN 1024
#define NPG 128
#define NB 8
#define KM 64
#define H 600
#define G 50
#define NL 6
#define NC 259           // coarse knots, d=(q-1)*D0, q=0..258
#define D0 (10.0f/256.0f)
#define SPLITK 4

__device__ float g_h[NN*H], g_x1[NN*H], g_msg[NN*H], g_m1[NN*H];
__device__ float g_part[SPLITK][NN*H];
__device__ float g_T[NL*NC*H], g_tmp[NL*NC*H], g_ea[NC*G], g_C[NC];
__device__ float g_pool[NB*H];
__device__ int   g_nbr[NN*KM], g_base[NN*KM], g_cnt[NN];
__device__ float g_w4[NN*KM*4];

__device__ __forceinline__ float sspf(float x){
    float r = (x > 0.f) ? (x + log1pf(expf(-x))) : log1pf(expf(x));
    return r - 0.69314718055994530942f;
}

// ---- graph build: 1 block per node, matches jax top_k(-dist2, K) ----
__global__ void build_graph(const float* __restrict__ pos){
    int i = blockIdx.x, b = i/NPG, il = i - b*NPG, j = threadIdx.x;
    __shared__ float sx[NPG], sy[NPG], sz[NPG], sd2[NPG];
    __shared__ int scnt;
    const float* pg = pos + (size_t)b*NPG*3;
    sx[j]=pg[j*3]; sy[j]=pg[j*3+1]; sz[j]=pg[j*3+2];
    if(j==0) scnt=0;
    __syncthreads();
    float dx=__fsub_rn(sx[il],sx[j]), dy=__fsub_rn(sy[il],sy[j]), dz=__fsub_rn(sz[il],sz[j]);
    float d2=__fadd_rn(__fadd_rn(__fmul_rn(dx,dx),__fmul_rn(dy,dy)),__fmul_rn(dz,dz));
    bool ok = (d2<=100.0f) && (j!=il);
    sd2[j] = ok ? d2 : 3.0e38f;
    __syncthreads();
    int rank=0;
    if(ok){
        #pragma unroll 8
        for(int t=0;t<NPG;t++){ float o=sd2[t]; rank += (o<d2)||(o==d2 && t<j); }
        atomicAdd(&scnt,1);
    }
    __syncthreads();
    if(j==0) g_cnt[i] = min(scnt,KM);
    if(ok && rank<KM){
        float d = sqrtf(d2);
        float u = d * (1.0f/D0);
        int s = (int)u; if(s>255) s=255; if(s<0) s=0;
        float t = u - (float)s;
        float t2=t*t, t3=t2*t;
        int e=i*KM+rank;
        g_nbr[e]=b*NPG+j; g_base[e]=s*H;
        g_w4[e*4+0]=0.5f*(-t3+2.f*t2-t);
        g_w4[e*4+1]=0.5f*(3.f*t3-5.f*t2+2.f);
        g_w4[e*4+2]=0.5f*(-3.f*t3+4.f*t2+t);
        g_w4[e*4+3]=0.5f*(t3-t2);
    }
}

// ---- gaussian smearing + cosine cutoff on coarse grid ----
__global__ void smear(){
    int idx = blockIdx.x*blockDim.x + threadIdx.x;
    if(idx >= NC*G) return;
    int q = idx/G, g = idx - q*G;
    float d = (float)(q-1)*D0;
    float step = 10.0f/49.0f;
    float x = d - (float)g*step;
    g_ea[idx] = expf((-0.5f/(step*step))*x*x);
    if(g==0) g_C[q] = 0.5f*(cosf(d*0.31415926535897932f)+1.0f);
}

__global__ void embed(const float* __restrict__ emb, const int* __restrict__ z){
    int idx = blockIdx.x*blockDim.x + threadIdx.x;
    if(idx >= NN*H) return;
    int i = idx/H;
    g_h[idx] = emb[z[i]*H + (idx - i*H)];
}

// ---- aggregation (float2 lanes): msg_i[h] = sum_k cubic(T_l,d_ik)[h]*x1[nbr][h] ----
__global__ void __launch_bounds__(320) agg(int l){
    int i = blockIdx.x, t = threadIdx.x;
    __shared__ int s_j[KM], s_b[KM], s_cnt;
    __shared__ float4 s_w[KM];
    if(t==0) s_cnt = g_cnt[i];
    if(t<KM){
        int e=i*KM+t;
        s_j[t]=g_nbr[e]*H; s_b[t]=g_base[e];
        s_w[t]=*reinterpret_cast<const float4*>(&g_w4[e*4]);
    }
    __syncthreads();
    if(t >= 300) return;
    int h = t*2;
    const float* T = g_T + (size_t)l*NC*H;
    int cnt = s_cnt;
    float ax = 0.f, ay = 0.f;
    #pragma unroll 2
    for(int k=0;k<cnt;k++){
        const float2* tp = reinterpret_cast<const float2*>(T + s_b[k] + h);
        float2 t0=__ldg(tp), t1=__ldg(tp+300), t2=__ldg(tp+600), t3=__ldg(tp+900);
        float2 x2=__ldg(reinterpret_cast<const float2*>(&g_x1[s_j[k]+h]));
        float4 w = s_w[k];
        float vx = w.x*t0.x + w.y*t1.x + w.z*t2.x + w.w*t3.x;
        float vy = w.x*t0.y + w.y*t1.y + w.z*t2.y + w.w*t3.y;
        ax = fmaf(vx, x2.x, ax);
        ay = fmaf(vy, x2.y, ay);
    }
    float2 o; o.x=ax; o.y=ay;
    *reinterpret_cast<float2*>(&g_msg[i*H+h]) = o;
}

// ---- batched SIMT fp32 GEMM (full K, fused epilogue), gridDim.z = batch ----
// EPI: 0 plain, 1 ssp, 3 *=extra[m] (extra shared across batch)
template<int EPI>
__global__ void __launch_bounds__(256) sgemm_b(const float* A, const float* B,
        const float* bias, const float* extra, float* Cm,
        int M, int N, int K, long sA, long sB, long sb, long sC){
    int zb = blockIdx.z;
    A  += (size_t)zb * sA;
    B  += (size_t)zb * sB;
    Cm += (size_t)zb * sC;
    if(bias) bias += (size_t)zb * sb;

    const int BM=64, BN=64, BK=16;
    __shared__ float As[BK][BM], Bs[BK][BN];
    int tid=threadIdx.x, tx=tid&15, ty=tid>>4;
    int m0=blockIdx.y*BM, n0=blockIdx.x*BN;
    int ar=tid>>2, ac=(tid&3)<<2, br=tid>>4, bc=(tid&15)<<2;
    float acc[4][4];
    #pragma unroll
    for(int a=0;a<4;a++)
        #pragma unroll
        for(int c=0;c<4;c++) acc[a][c]=0.f;
    for(int k0=0;k0<K;k0+=BK){
        int gm=m0+ar;
        #pragma unroll
        for(int u=0;u<4;u++){
            int gk=k0+ac+u;
            As[ac+u][ar] = (gm<M && gk<K) ? A[(size_t)gm*K+gk] : 0.f;
        }
        int gk2=k0+br;
        #pragma unroll
        for(int u=0;u<4;u++){
            int gn=n0+bc+u;
            Bs[br][bc+u] = (gk2<K && gn<N) ? B[(size_t)gk2*N+gn] : 0.f;
        }
        __syncthreads();
        #pragma unroll
        for(int kk=0;kk<BK;kk++){
            float4 av=*reinterpret_cast<const float4*>(&As[kk][ty<<2]);
            float4 bv=*reinterpret_cast<const float4*>(&Bs[kk][tx<<2]);
            float a0=av.x,a1=av.y,a2=av.z,a3=av.w;
            float b0=bv.x,b1=bv.y,b2=bv.z,b3=bv.w;
            acc[0][0]=fmaf(a0,b0,acc[0][0]); acc[0][1]=fmaf(a0,b1,acc[0][1]);
            acc[0][2]=fmaf(a0,b2,acc[0][2]); acc[0][3]=fmaf(a0,b3,acc[0][3]);
            acc[1][0]=fmaf(a1,b0,acc[1][0]); acc[1][1]=fmaf(a1,b1,acc[1][1]);
            acc[1][2]=fmaf(a1,b2,acc[1][2]); acc[1][3]=fmaf(a1,b3,acc[1][3]);
            acc[2][0]=fmaf(a2,b0,acc[2][0]); acc[2][1]=fmaf(a2,b1,acc[2][1]);
            acc[2][2]=fmaf(a2,b2,acc[2][2]); acc[2][3]=fmaf(a2,b3,acc[2][3]);
            acc[3][0]=fmaf(a3,b0,acc[3][0]); acc[3][1]=fmaf(a3,b1,acc[3][1]);
            acc[3][2]=fmaf(a3,b2,acc[3][2]); acc[3][3]=fmaf(a3,b3,acc[3][3]);
        }
        __syncthreads();
    }
    #pragma unroll
    for(int ii=0;ii<4;ii++){
        int m=m0+(ty<<2)+ii;
        if(m>=M) continue;
        #pragma unroll
        for(int jj=0;jj<4;jj++){
            int n=n0+(tx<<2)+jj;
            if(n>=N) continue;
            float v=acc[ii][jj];
            if(bias) v += bias[n];
            if(EPI==1) v = sspf(v);
            else if(EPI==3) v *= extra[m];
            Cm[(size_t)m*N+n]=v;
        }
    }
}

// ---- split-K SIMT fp32 GEMM: writes partials g_part[z] (deterministic) ----
__global__ void __launch_bounds__(256) sgemm_sk(const float* __restrict__ A,
        const float* __restrict__ B, float* __restrict__ P,
        int M, int N, int K){
    int z = blockIdx.z;
    int kchunk = (K + SPLITK - 1) / SPLITK;
    int kbeg = z * kchunk;
    int kend = min(K, kbeg + kchunk);
    float* Cm = P + (size_t)z * M * N;

    const int BM=64, BN=64, BK=16;
    __shared__ float As[BK][BM], Bs[BK][BN];
    int tid=threadIdx.x, tx=tid&15, ty=tid>>4;
    int m0=blockIdx.y*BM, n0=blockIdx.x*BN;
    int ar=tid>>2, ac=(tid&3)<<2, br=tid>>4, bc=(tid&15)<<2;
    float acc[4][4];
    #pragma unroll
    for(int a=0;a<4;a++)
        #pragma unroll
        for(int c=0;c<4;c++) acc[a][c]=0.f;
    for(int k0=kbeg;k0<kend;k0+=BK){
        int gm=m0+ar;
        #pragma unroll
        for(int u=0;u<4;u++){
            int gk=k0+ac+u;
            As[ac+u][ar] = (gm<M && gk<kend) ? A[(size_t)gm*K+gk] : 0.f;
        }
        int gk2=k0+br;
        #pragma unroll
        for(int u=0;u<4;u++){
            int gn=n0+bc+u;
            Bs[br][bc+u] = (gk2<kend && gn<N) ? B[(size_t)gk2*N+gn] : 0.f;
        }
        __syncthreads();
        #pragma unroll
        for(int kk=0;kk<BK;kk++){
            float4 av=*reinterpret_cast<const float4*>(&As[kk][ty<<2]);
            float4 bv=*reinterpret_cast<const float4*>(&Bs[kk][tx<<2]);
            float a0=av.x,a1=av.y,a2=av.z,a3=av.w;
            float b0=bv.x,b1=bv.y,b2=bv.z,b3=bv.w;
            acc[0][0]=fmaf(a0,b0,acc[0][0]); acc[0][1]=fmaf(a0,b1,acc[0][1]);
            acc[0][2]=fmaf(a0,b2,acc[0][2]); acc[0][3]=fmaf(a0,b3,acc[0][3]);
            acc[1][0]=fmaf(a1,b0,acc[1][0]); acc[1][1]=fmaf(a1,b1,acc[1][1]);
            acc[1][2]=fmaf(a1,b2,acc[1][2]); acc[1][3]=fmaf(a1,b3,acc[1][3]);
            acc[2][0]=fmaf(a2,b0,acc[2][0]); acc[2][1]=fmaf(a2,b1,acc[2][1]);
            acc[2][2]=fmaf(a2,b2,acc[2][2]); acc[2][3]=fmaf(a2,b3,acc[2][3]);
            acc[3][0]=fmaf(a3,b0,acc[3][0]); acc[3][1]=fmaf(a3,b1,acc[3][1]);
            acc[3][2]=fmaf(a3,b2,acc[3][2]); acc[3][3]=fmaf(a3,b3,acc[3][3]);
        }
        __syncthreads();
    }
    #pragma unroll
    for(int ii=0;ii<4;ii++){
        int m=m0+(ty<<2)+ii;
        if(m>=M) continue;
        #pragma unroll
        for(int jj=0;jj<4;jj++){
            int n=n0+(tx<<2)+jj;
            if(n>=N) continue;
            Cm[(size_t)m*N+n]=acc[ii][jj];
        }
    }
}

// ---- combine split-K partials + fused epilogue (float4, fixed order) ----
// EPI: 0 plain, 1 ssp, 2 += extra (residual)
template<int EPI>
__global__ void reduce_epi(const float* __restrict__ bias,
        const float* __restrict__ extra, float* __restrict__ Cm){
    int idx = blockIdx.x*blockDim.x + threadIdx.x;   // float4 index
    if(idx >= NN*H/4) return;
    const float4* p0 = reinterpret_cast<const float4*>(g_part[0]);
    const float4* p1 = reinterpret_cast<const float4*>(g_part[1]);
    const float4* p2 = reinterpret_cast<const float4*>(g_part[2]);
    const float4* p3 = reinterpret_cast<const float4*>(g_part[3]);
    float4 a = p0[idx], b = p1[idx], c = p2[idx], d = p3[idx];
    float4 v;
    v.x = ((a.x + b.x) + (c.x + d.x));
    v.y = ((a.y + b.y) + (c.y + d.y));
    v.z = ((a.z + b.z) + (c.z + d.z));
    v.w = ((a.w + b.w) + (c.w + d.w));
    if(bias){
        int n = (idx*4) % H;     // H % 4 == 0, so float4 never crosses a row
        const float4 bb = *reinterpret_cast<const float4*>(bias + n);
        v.x += bb.x; v.y += bb.y; v.z += bb.z; v.w += bb.w;
    }
    if(EPI==1){
        v.x = sspf(v.x); v.y = sspf(v.y); v.z = sspf(v.z); v.w = sspf(v.w);
    } else if(EPI==2){
        const float4 e = reinterpret_cast<const float4*>(extra)[idx];
        v.x += e.x; v.y += e.y; v.z += e.z; v.w += e.w;
    }
    reinterpret_cast<float4*>(Cm)[idx] = v;
}

__global__ void pool(){
    int idx = blockIdx.x*blockDim.x + threadIdx.x;
    if(idx >= NB*H) return;
    int b = idx/H, h = idx - b*H;
    const float* p = g_h + (size_t)b*NPG*H + h;
    float s = 0.f;
    #pragma unroll 8
    for(int n=0;n<NPG;n++) s += p[(size_t)n*H];
    g_pool[idx] = s * (1.0f/NPG);
}

__global__ void final_lin(const float* __restrict__ pw, const float* __restrict__ pb,
                          float* __restrict__ out){
    int idx = blockIdx.x*blockDim.x + threadIdx.x;
    if(idx >= NB*H) return;
    int b = idx/H, n = idx - b*H;
    const float* pr = g_pool + b*H;
    float s = pb[n];
    for(int k=0;k<H;k++) s = fmaf(pr[k], pw[(size_t)k*H+n], s);
    out[idx] = s;
}

extern "C" void kernel_launch(void* const* d_in, const int* in_sizes, int n_in,
                              void* d_out, int out_size){
    // dict order: z,pos,emb,w1,b1,w2,b2,lin1,l2w,l2b,ilw,ilb,pw,pb
    int map[14] = {0,1,2,3,4,5,6,7,8,9,10,11,12,13};
    if(!(in_sizes[0]==1024 && in_sizes[1]==3072)){
        int sig[14] = {13,0,1,2,3,4,5,6,7,8,9,10,11,12};
        for(int i=0;i<14;i++) map[i]=sig[i];
    }
    const int*   z    = (const int*)  d_in[map[0]];
    const float* posv = (const float*)d_in[map[1]];
    const float* emb  = (const float*)d_in[map[2]];
    const float* w1   = (const float*)d_in[map[3]];
    const float* b1   = (const float*)d_in[map[4]];
    const float* w2   = (const float*)d_in[map[5]];
    const float* b2   = (const float*)d_in[map[6]];
    const float* lin1 = (const float*)d_in[map[7]];
    const float* l2w  = (const float*)d_in[map[8]];
    const float* l2b  = (const float*)d_in[map[9]];
    const float* ilw  = (const float*)d_in[map[10]];
    const float* ilb  = (const float*)d_in[map[11]];
    const float* pw   = (const float*)d_in[map[12]];
    const float* pb   = (const float*)d_in[map[13]];
    float* out = (float*)d_out;

    float *p_h,*p_x1,*p_msg,*p_m1,*p_T,*p_tmp,*p_ea,*p_C,*p_part;
    cudaGetSymbolAddress((void**)&p_h,   g_h);
    cudaGetSymbolAddress((void**)&p_x1,  g_x1);
    cudaGetSymbolAddress((void**)&p_msg, g_msg);
    cudaGetSymbolAddress((void**)&p_m1,  g_m1);
    cudaGetSymbolAddress((void**)&p_T,   g_T);
    cudaGetSymbolAddress((void**)&p_tmp, g_tmp);
    cudaGetSymbolAddress((void**)&p_ea,  g_ea);
    cudaGetSymbolAddress((void**)&p_C,   g_C);
    cudaGetSymbolAddress((void**)&p_part,g_part);

    build_graph<<<NN, NPG>>>(posv);
    smear<<<(NC*G+255)/256, 256>>>();
    embed<<<(NN*H+255)/256, 256>>>(emb, z);

    // coarse filter tables for all 6 layers, batched over gridDim.z
    dim3 gT((H+63)/64, (NC+63)/64, NL);
    sgemm_b<1><<<gT,256>>>(p_ea, w1, b1, nullptr, p_tmp,
                           NC, H, G, 0L, (long)G*H, (long)H, (long)NC*H);
    sgemm_b<3><<<gT,256>>>(p_tmp, w2, b2, p_C, p_T,
                           NC, H, H, (long)NC*H, (long)H*H, (long)H, (long)NC*H);

    dim3 gSK((H+63)/64, (NN+63)/64, SPLITK);   // 10 x 16 x 4 = 640 blocks
    int rblocks = (NN*H/4 + 255)/256;

    for(int l=0;l<NL;l++){
        // x1 = h @ lin1 (no bias)
        sgemm_sk<<<gSK,256>>>(p_h, lin1+(size_t)l*H*H, p_part, NN, H, H);
        reduce_epi<0><<<rblocks,256>>>(nullptr, nullptr, p_x1);
        agg<<<NN, 320>>>(l);
        // m1 = ssp(msg @ l2w + l2b)
        sgemm_sk<<<gSK,256>>>(p_msg, l2w+(size_t)l*H*H, p_part, NN, H, H);
        reduce_epi<1><<<rblocks,256>>>(l2b+(size_t)l*H, nullptr, p_m1);
        // h = h + (m1 @ ilw + ilb)
        sgemm_sk<<<gSK,256>>>(p_m1, ilw+(size_t)l*H*H, p_part, NN, H, H);
        reduce_epi<2><<<rblocks,256>>>(ilb+(size_t)l*H, p_h, p_h);
    }
    pool<<<(NB*H+255)/256, 256>>>();
    final_lin<<<(NB*H+255)/256, 256>>>(pw, pb, out);
}

// round 6
// speedup vs baseline: 2.0633x; 1.2409x over previous
#include <cuda_runtime.h>
#include <cuda_fp16.h>
#include <math.h>

#define NN 1024
#define NPG 128
#define NB 8
#define KM 64
#define H 600
#define G 50
#define NL 6
#define NC 259           // coarse knots, d=(q-1)*D0, q=0..258
#define D0 (10.0f/256.0f)
#define SPLITK 4
#define KSLICE 152       // multiple of 4 (alignment); 4*152 >= 600

__device__ float g_h[NN*H], g_x1[NN*H], g_msg[NN*H], g_m1[NN*H];
__device__ float g_part[SPLITK][NN*H];
__device__ float g_T[NL*NC*H], g_tmp[NL*NC*H], g_ea[NC*G], g_C[NC];
__device__ __half g_Th[NL*NC*H];
__device__ float g_pool[NB*H];
__device__ int   g_nbr[NN*KM], g_base[NN*KM], g_cnt[NN];
__device__ float g_w4[NN*KM*4];

__device__ __forceinline__ float sspf(float x){
    float r = (x > 0.f) ? (x + log1pf(expf(-x))) : log1pf(expf(x));
    return r - 0.69314718055994530942f;
}

// ---- graph build: 1 block per node, matches jax top_k(-dist2, K) ----
__global__ void build_graph(const float* __restrict__ pos){
    int i = blockIdx.x, b = i/NPG, il = i - b*NPG, j = threadIdx.x;
    __shared__ float sx[NPG], sy[NPG], sz[NPG], sd2[NPG];
    __shared__ int scnt;
    const float* pg = pos + (size_t)b*NPG*3;
    sx[j]=pg[j*3]; sy[j]=pg[j*3+1]; sz[j]=pg[j*3+2];
    if(j==0) scnt=0;
    __syncthreads();
    float dx=__fsub_rn(sx[il],sx[j]), dy=__fsub_rn(sy[il],sy[j]), dz=__fsub_rn(sz[il],sz[j]);
    float d2=__fadd_rn(__fadd_rn(__fmul_rn(dx,dx),__fmul_rn(dy,dy)),__fmul_rn(dz,dz));
    bool ok = (d2<=100.0f) && (j!=il);
    sd2[j] = ok ? d2 : 3.0e38f;
    __syncthreads();
    int rank=0;
    if(ok){
        #pragma unroll 8
        for(int t=0;t<NPG;t++){ float o=sd2[t]; rank += (o<d2)||(o==d2 && t<j); }
        atomicAdd(&scnt,1);
    }
    __syncthreads();
    if(j==0) g_cnt[i] = min(scnt,KM);
    if(ok && rank<KM){
        float d = sqrtf(d2);
        float u = d * (1.0f/D0);
        int s = (int)u; if(s>255) s=255; if(s<0) s=0;
        float t = u - (float)s;
        float t2=t*t, t3=t2*t;
        int e=i*KM+rank;
        g_nbr[e]=b*NPG+j; g_base[e]=s*H;
        g_w4[e*4+0]=0.5f*(-t3+2.f*t2-t);
        g_w4[e*4+1]=0.5f*(3.f*t3-5.f*t2+2.f);
        g_w4[e*4+2]=0.5f*(-3.f*t3+4.f*t2+t);
        g_w4[e*4+3]=0.5f*(t3-t2);
    }
}

// ---- gaussian smearing + cosine cutoff on coarse grid ----
__global__ void smear(){
    int idx = blockIdx.x*blockDim.x + threadIdx.x;
    if(idx >= NC*G) return;
    int q = idx/G, g = idx - q*G;
    float d = (float)(q-1)*D0;
    float step = 10.0f/49.0f;
    float x = d - (float)g*step;
    g_ea[idx] = expf((-0.5f/(step*step))*x*x);
    if(g==0) g_C[q] = 0.5f*(cosf(d*0.31415926535897932f)+1.0f);
}

__global__ void embed(const float* __restrict__ emb, const int* __restrict__ z){
    int idx = blockIdx.x*blockDim.x + threadIdx.x;
    if(idx >= NN*H) return;
    int i = idx/H;
    g_h[idx] = emb[z[i]*H + (idx - i*H)];
}

__global__ void to_half(){
    int idx = blockIdx.x*blockDim.x + threadIdx.x;
    if(idx >= NL*NC*H) return;
    g_Th[idx] = __float2half_rn(g_T[idx]);
}

// ---- aggregation (fp16 table, float accumulate) ----
__global__ void __launch_bounds__(320) agg(int l){
    int i = blockIdx.x, t = threadIdx.x;
    __shared__ int s_j[KM], s_b[KM], s_cnt;
    __shared__ float4 s_w[KM];
    if(t==0) s_cnt = g_cnt[i];
    if(t<KM){
        int e=i*KM+t;
        s_j[t]=g_nbr[e]*H; s_b[t]=g_base[e];
        s_w[t]=*reinterpret_cast<const float4*>(&g_w4[e*4]);
    }
    __syncthreads();
    if(t >= 300) return;
    int h = t*2;
    const __half* T = g_Th + (size_t)l*NC*H;
    int cnt = s_cnt;
    float ax = 0.f, ay = 0.f;
    #pragma unroll 2
    for(int k=0;k<cnt;k++){
        const __half2* tp = reinterpret_cast<const __half2*>(T + s_b[k] + h);
        float2 t0=__half22float2(__ldg(tp));
        float2 t1=__half22float2(__ldg(tp+300));
        float2 t2=__half22float2(__ldg(tp+600));
        float2 t3=__half22float2(__ldg(tp+900));
        float2 x2=__ldg(reinterpret_cast<const float2*>(&g_x1[s_j[k]+h]));
        float4 w = s_w[k];
        float vx = w.x*t0.x + w.y*t1.x + w.z*t2.x + w.w*t3.x;
        float vy = w.x*t0.y + w.y*t1.y + w.z*t2.y + w.w*t3.y;
        ax = fmaf(vx, x2.x, ax);
        ay = fmaf(vy, x2.y, ay);
    }
    float2 o; o.x=ax; o.y=ay;
    *reinterpret_cast<float2*>(&g_msg[i*H+h]) = o;
}

// ---- batched SIMT fp32 GEMM for table build (small) ----
// EPI: 0 plain, 1 ssp, 3 *=extra[m]
template<int EPI>
__global__ void __launch_bounds__(256) sgemm_b(const float* A, const float* B,
        const float* bias, const float* extra, float* Cm,
        int M, int N, int K, long sA, long sB, long sb, long sC){
    int zb = blockIdx.z;
    A  += (size_t)zb * sA;
    B  += (size_t)zb * sB;
    Cm += (size_t)zb * sC;
    if(bias) bias += (size_t)zb * sb;

    const int BM=64, BN=64, BK=16;
    __shared__ float As[BK][BM], Bs[BK][BN];
    int tid=threadIdx.x, tx=tid&15, ty=tid>>4;
    int m0=blockIdx.y*BM, n0=blockIdx.x*BN;
    int ar=tid>>2, ac=(tid&3)<<2, br=tid>>4, bc=(tid&15)<<2;
    float acc[4][4];
    #pragma unroll
    for(int a=0;a<4;a++)
        #pragma unroll
        for(int c=0;c<4;c++) acc[a][c]=0.f;
    for(int k0=0;k0<K;k0+=BK){
        int gm=m0+ar;
        #pragma unroll
        for(int u=0;u<4;u++){
            int gk=k0+ac+u;
            As[ac+u][ar] = (gm<M && gk<K) ? A[(size_t)gm*K+gk] : 0.f;
        }
        int gk2=k0+br;
        #pragma unroll
        for(int u=0;u<4;u++){
            int gn=n0+bc+u;
            Bs[br][bc+u] = (gk2<K && gn<N) ? B[(size_t)gk2*N+gn] : 0.f;
        }
        __syncthreads();
        #pragma unroll
        for(int kk=0;kk<BK;kk++){
            float4 av=*reinterpret_cast<const float4*>(&As[kk][ty<<2]);
            float4 bv=*reinterpret_cast<const float4*>(&Bs[kk][tx<<2]);
            float a0=av.x,a1=av.y,a2=av.z,a3=av.w;
            float b0=bv.x,b1=bv.y,b2=bv.z,b3=bv.w;
            acc[0][0]=fmaf(a0,b0,acc[0][0]); acc[0][1]=fmaf(a0,b1,acc[0][1]);
            acc[0][2]=fmaf(a0,b2,acc[0][2]); acc[0][3]=fmaf(a0,b3,acc[0][3]);
            acc[1][0]=fmaf(a1,b0,acc[1][0]); acc[1][1]=fmaf(a1,b1,acc[1][1]);
            acc[1][2]=fmaf(a1,b2,acc[1][2]); acc[1][3]=fmaf(a1,b3,acc[1][3]);
            acc[2][0]=fmaf(a2,b0,acc[2][0]); acc[2][1]=fmaf(a2,b1,acc[2][1]);
            acc[2][2]=fmaf(a2,b2,acc[2][2]); acc[2][3]=fmaf(a2,b3,acc[2][3]);
            acc[3][0]=fmaf(a3,b0,acc[3][0]); acc[3][1]=fmaf(a3,b1,acc[3][1]);
            acc[3][2]=fmaf(a3,b2,acc[3][2]); acc[3][3]=fmaf(a3,b3,acc[3][3]);
        }
        __syncthreads();
    }
    #pragma unroll
    for(int ii=0;ii<4;ii++){
        int m=m0+(ty<<2)+ii;
        if(m>=M) continue;
        #pragma unroll
        for(int jj=0;jj<4;jj++){
            int n=n0+(tx<<2)+jj;
            if(n>=N) continue;
            float v=acc[ii][jj];
            if(bias) v += bias[n];
            if(EPI==1) v = sspf(v);
            else if(EPI==3) v *= extra[m];
            Cm[(size_t)m*N+n]=v;
        }
    }
}

// ---- node GEMM: fixed M=1024, N=600, K=600; 128x64 tile, 8x8 micro,
//      split-K=4 (152-wide slices), writes partials ----
__global__ void __launch_bounds__(128) sgemm_sk(const float* __restrict__ A,
        const float* __restrict__ B, float* __restrict__ P){
    const int M = NN, N = H, K = H;
    const int BM=128, BN=64, BK=16;
    int z = blockIdx.z;
    int kbeg = z * KSLICE;
    int kend = min(K, kbeg + KSLICE);
    float* Cm = P + (size_t)z * M * N;

    __shared__ float As[BK][BM];
    __shared__ float Bs[BK][BN];
    int tid = threadIdx.x;
    int tx = tid & 7;            // 8 col groups of 8
    int ty = tid >> 3;           // 16 row groups of 8
    int m0 = blockIdx.y * BM;
    int n0 = blockIdx.x * BN;

    float acc[8][8];
    #pragma unroll
    for(int a=0;a<8;a++)
        #pragma unroll
        for(int c=0;c<8;c++) acc[a][c]=0.f;

    int brow = tid >> 4;         // 0..7, B k-rows brow and brow+8
    int bcol = (tid & 15) << 2;  // 0..60

    for(int k0 = kbeg; k0 < kend; k0 += BK){
        // A: thread loads row m0+tid, 16 k's as 4 float4 (k aligned to 4)
        {
            const float* ar = A + (size_t)(m0 + tid) * K;
            #pragma unroll
            for(int v=0; v<4; v++){
                int gk = k0 + v*4;
                float4 a4 = (gk < kend) ? *reinterpret_cast<const float4*>(ar + gk)
                                        : make_float4(0.f,0.f,0.f,0.f);
                As[v*4+0][tid] = a4.x;
                As[v*4+1][tid] = a4.y;
                As[v*4+2][tid] = a4.z;
                As[v*4+3][tid] = a4.w;
            }
        }
        // B: thread loads 2 rows x one float4
        #pragma unroll
        for(int s=0; s<2; s++){
            int gk = k0 + brow + s*8;
            int gn = n0 + bcol;
            float4 b4 = (gk < kend && gn < N)
                ? *reinterpret_cast<const float4*>(B + (size_t)gk*N + gn)
                : make_float4(0.f,0.f,0.f,0.f);
            *reinterpret_cast<float4*>(&Bs[brow + s*8][bcol]) = b4;
        }
        __syncthreads();
        #pragma unroll
        for(int kk=0; kk<BK; kk++){
            float a[8], b[8];
            float4 av0 = *reinterpret_cast<const float4*>(&As[kk][ty*8]);
            float4 av1 = *reinterpret_cast<const float4*>(&As[kk][ty*8+4]);
            float4 bv0 = *reinterpret_cast<const float4*>(&Bs[kk][tx*8]);
            float4 bv1 = *reinterpret_cast<const float4*>(&Bs[kk][tx*8+4]);
            a[0]=av0.x;a[1]=av0.y;a[2]=av0.z;a[3]=av0.w;
            a[4]=av1.x;a[5]=av1.y;a[6]=av1.z;a[7]=av1.w;
            b[0]=bv0.x;b[1]=bv0.y;b[2]=bv0.z;b[3]=bv0.w;
            b[4]=bv1.x;b[5]=bv1.y;b[6]=bv1.z;b[7]=bv1.w;
            #pragma unroll
            for(int ii=0;ii<8;ii++)
                #pragma unroll
                for(int jj=0;jj<8;jj++)
                    acc[ii][jj] = fmaf(a[ii], b[jj], acc[ii][jj]);
        }
        __syncthreads();
    }

    // epilogue: rows always < 1024; guard cols (chunks of 4, aligned)
    #pragma unroll
    for(int ii=0;ii<8;ii++){
        int m = m0 + ty*8 + ii;
        float* cr = Cm + (size_t)m * N;
        #pragma unroll
        for(int jc=0;jc<2;jc++){
            int n = n0 + tx*8 + jc*4;
            if(n < N){
                float4 v;
                v.x = acc[ii][jc*4+0]; v.y = acc[ii][jc*4+1];
                v.z = acc[ii][jc*4+2]; v.w = acc[ii][jc*4+3];
                *reinterpret_cast<float4*>(cr + n) = v;
            }
        }
    }
}

// ---- combine split-K partials + fused epilogue (float4, fixed order) ----
// EPI: 0 plain, 1 ssp, 2 += extra (residual)
template<int EPI>
__global__ void reduce_epi(const float* __restrict__ bias,
        const float* __restrict__ extra, float* __restrict__ Cm){
    int idx = blockIdx.x*blockDim.x + threadIdx.x;   // float4 index
    if(idx >= NN*H/4) return;
    const float4* p0 = reinterpret_cast<const float4*>(g_part[0]);
    const float4* p1 = reinterpret_cast<const float4*>(g_part[1]);
    const float4* p2 = reinterpret_cast<const float4*>(g_part[2]);
    const float4* p3 = reinterpret_cast<const float4*>(g_part[3]);
    float4 a = p0[idx], b = p1[idx], c = p2[idx], d = p3[idx];
    float4 v;
    v.x = ((a.x + b.x) + (c.x + d.x));
    v.y = ((a.y + b.y) + (c.y + d.y));
    v.z = ((a.z + b.z) + (c.z + d.z));
    v.w = ((a.w + b.w) + (c.w + d.w));
    if(bias){
        int n = (idx*4) % H;     // H % 4 == 0, so float4 never crosses a row
        const float4 bb = *reinterpret_cast<const float4*>(bias + n);
        v.x += bb.x; v.y += bb.y; v.z += bb.z; v.w += bb.w;
    }
    if(EPI==1){
        v.x = sspf(v.x); v.y = sspf(v.y); v.z = sspf(v.z); v.w = sspf(v.w);
    } else if(EPI==2){
        const float4 e = reinterpret_cast<const float4*>(extra)[idx];
        v.x += e.x; v.y += e.y; v.z += e.z; v.w += e.w;
    }
    reinterpret_cast<float4*>(Cm)[idx] = v;
}

__global__ void pool(){
    int idx = blockIdx.x*blockDim.x + threadIdx.x;
    if(idx >= NB*H) return;
    int b = idx/H, h = idx - b*H;
    const float* p = g_h + (size_t)b*NPG*H + h;
    float s = 0.f;
    #pragma unroll 8
    for(int n=0;n<NPG;n++) s += p[(size_t)n*H];
    g_pool[idx] = s * (1.0f/NPG);
}

__global__ void final_lin(const float* __restrict__ pw, const float* __restrict__ pb,
                          float* __restrict__ out){
    int idx = blockIdx.x*blockDim.x + threadIdx.x;
    if(idx >= NB*H) return;
    int b = idx/H, n = idx - b*H;
    const float* pr = g_pool + b*H;
    float s = pb[n];
    for(int k=0;k<H;k++) s = fmaf(pr[k], pw[(size_t)k*H+n], s);
    out[idx] = s;
}

extern "C" void kernel_launch(void* const* d_in, const int* in_sizes, int n_in,
                              void* d_out, int out_size){
    // dict order: z,pos,emb,w1,b1,w2,b2,lin1,l2w,l2b,ilw,ilb,pw,pb
    int map[14] = {0,1,2,3,4,5,6,7,8,9,10,11,12,13};
    if(!(in_sizes[0]==1024 && in_sizes[1]==3072)){
        int sig[14] = {13,0,1,2,3,4,5,6,7,8,9,10,11,12};
        for(int i=0;i<14;i++) map[i]=sig[i];
    }
    const int*   z    = (const int*)  d_in[map[0]];
    const float* posv = (const float*)d_in[map[1]];
    const float* emb  = (const float*)d_in[map[2]];
    const float* w1   = (const float*)d_in[map[3]];
    const float* b1   = (const float*)d_in[map[4]];
    const float* w2   = (const float*)d_in[map[5]];
    const float* b2   = (const float*)d_in[map[6]];
    const float* lin1 = (const float*)d_in[map[7]];
    const float* l2w  = (const float*)d_in[map[8]];
    const float* l2b  = (const float*)d_in[map[9]];
    const float* ilw  = (const float*)d_in[map[10]];
    const float* ilb  = (const float*)d_in[map[11]];
    const float* pw   = (const float*)d_in[map[12]];
    const float* pb   = (const float*)d_in[map[13]];
    float* out = (float*)d_out;

    float *p_h,*p_x1,*p_msg,*p_m1,*p_T,*p_tmp,*p_ea,*p_C,*p_part;
    cudaGetSymbolAddress((void**)&p_h,   g_h);
    cudaGetSymbolAddress((void**)&p_x1,  g_x1);
    cudaGetSymbolAddress((void**)&p_msg, g_msg);
    cudaGetSymbolAddress((void**)&p_m1,  g_m1);
    cudaGetSymbolAddress((void**)&p_T,   g_T);
    cudaGetSymbolAddress((void**)&p_tmp, g_tmp);
    cudaGetSymbolAddress((void**)&p_ea,  g_ea);
    cudaGetSymbolAddress((void**)&p_C,   g_C);
    cudaGetSymbolAddress((void**)&p_part,g_part);

    build_graph<<<NN, NPG>>>(posv);
    smear<<<(NC*G+255)/256, 256>>>();
    embed<<<(NN*H+255)/256, 256>>>(emb, z);

    // coarse filter tables for all 6 layers, batched over gridDim.z
    dim3 gT((H+63)/64, (NC+63)/64, NL);
    sgemm_b<1><<<gT,256>>>(p_ea, w1, b1, nullptr, p_tmp,
                           NC, H, G, 0L, (long)G*H, (long)H, (long)NC*H);
    sgemm_b<3><<<gT,256>>>(p_tmp, w2, b2, p_C, p_T,
                           NC, H, H, (long)NC*H, (long)H*H, (long)H, (long)NC*H);
    to_half<<<(NL*NC*H+255)/256, 256>>>();

    dim3 gSK((H+63)/64, NN/128, SPLITK);   // 10 x 8 x 4 = 320 blocks
    int rblocks = (NN*H/4 + 255)/256;

    for(int l=0;l<NL;l++){
        // x1 = h @ lin1 (no bias)
        sgemm_sk<<<gSK,128>>>(p_h, lin1+(size_t)l*H*H, p_part);
        reduce_epi<0><<<rblocks,256>>>(nullptr, nullptr, p_x1);
        agg<<<NN, 320>>>(l);
        // m1 = ssp(msg @ l2w + l2b)
        sgemm_sk<<<gSK,128>>>(p_msg, l2w+(size_t)l*H*H, p_part);
        reduce_epi<1><<<rblocks,256>>>(l2b+(size_t)l*H, nullptr, p_m1);
        // h = h + (m1 @ ilw + ilb)
        sgemm_sk<<<gSK,128>>>(p_m1, ilw+(size_t)l*H*H, p_part);
        reduce_epi<2><<<rblocks,256>>>(ilb+(size_t)l*H, p_h, p_h);
    }
    pool<<<(NB*H+255)/256, 256>>>();
    final_lin<<<(NB*H+255)/256, 256>>>(pw, pb, out);
}

// round 7
// speedup vs baseline: 2.0674x; 1.0020x over previous
#include <cuda_runtime.h>
#include <cuda_fp16.h>
#include <math.h>

#define NN 1024
#define NPG 128
#define NB 8
#define KM 64
#define H 600
#define G 50
#define NL 6
#define NC 259           // coarse knots, d=(q-1)*D0, q=0..258
#define D0 (10.0f/256.0f)
#define PF 4096          // fine intervals; knots 0..4096 over [0,10]
#define PFP1 4097
#define SPLITK 6
#define KSLICE 100       // 6*100 = 600 exactly (multiple of 4)

__device__ float g_h[NN*H], g_msg[NN*H], g_m1[NN*H];
__device__ __half g_x1h[NN*H];
__device__ float g_part[SPLITK][NN*H];
__device__ float g_T[NL*NC*H], g_tmp[NL*NC*H], g_ea[NC*G], g_C[NC];
__device__ __half g_fine[(size_t)NL*PFP1*H];   // ~29.5 MB
__device__ float g_pool[NB*H];
__device__ int   g_nbr[NN*KM], g_base[NN*KM], g_cnt[NN];
__device__ float g_w1f[NN*KM];

__device__ __forceinline__ float sspf(float x){
    float r = (x > 0.f) ? (x + log1pf(expf(-x))) : log1pf(expf(x));
    return r - 0.69314718055994530942f;
}

// ---- graph build: 1 block per node, matches jax top_k(-dist2, K) ----
__global__ void build_graph(const float* __restrict__ pos){
    int i = blockIdx.x, b = i/NPG, il = i - b*NPG, j = threadIdx.x;
    __shared__ float sx[NPG], sy[NPG], sz[NPG], sd2[NPG];
    __shared__ int scnt;
    const float* pg = pos + (size_t)b*NPG*3;
    sx[j]=pg[j*3]; sy[j]=pg[j*3+1]; sz[j]=pg[j*3+2];
    if(j==0) scnt=0;
    __syncthreads();
    float dx=__fsub_rn(sx[il],sx[j]), dy=__fsub_rn(sy[il],sy[j]), dz=__fsub_rn(sz[il],sz[j]);
    float d2=__fadd_rn(__fadd_rn(__fmul_rn(dx,dx),__fmul_rn(dy,dy)),__fmul_rn(dz,dz));
    bool ok = (d2<=100.0f) && (j!=il);
    sd2[j] = ok ? d2 : 3.0e38f;
    __syncthreads();
    int rank=0;
    if(ok){
        #pragma unroll 8
        for(int t=0;t<NPG;t++){ float o=sd2[t]; rank += (o<d2)||(o==d2 && t<j); }
        atomicAdd(&scnt,1);
    }
    __syncthreads();
    if(j==0) g_cnt[i] = min(scnt,KM);
    if(ok && rank<KM){
        float d = sqrtf(d2);
        float u = d * ((float)PF / 10.0f);
        int p = (int)u; if(p > PF-1) p = PF-1; if(p < 0) p = 0;
        int e=i*KM+rank;
        g_nbr[e]=b*NPG+j;
        g_base[e]=p*H;
        g_w1f[e]=u-(float)p;
    }
}

// ---- gaussian smearing + cosine cutoff on coarse grid ----
__global__ void smear(){
    int idx = blockIdx.x*blockDim.x + threadIdx.x;
    if(idx >= NC*G) return;
    int q = idx/G, g = idx - q*G;
    float d = (float)(q-1)*D0;
    float step = 10.0f/49.0f;
    float x = d - (float)g*step;
    g_ea[idx] = expf((-0.5f/(step*step))*x*x);
    if(g==0) g_C[q] = 0.5f*(cosf(d*0.31415926535897932f)+1.0f);
}

__global__ void embed(const float* __restrict__ emb, const int* __restrict__ z){
    int idx = blockIdx.x*blockDim.x + threadIdx.x;
    if(idx >= NN*H) return;
    int i = idx/H;
    g_h[idx] = emb[z[i]*H + (idx - i*H)];
}

// ---- 16x Catmull-Rom upsample coarse fp32 -> fine fp16 ----
__global__ void upsample(){
    int idx = blockIdx.x*blockDim.x + threadIdx.x;
    if(idx >= PFP1*H) return;
    int l = blockIdx.y;
    int f = idx / H;
    int h = idx - f*H;
    int s = f >> 4; if(s > 255) s = 255;
    float t = (float)(f - (s<<4)) * (1.0f/16.0f);
    const float* c = g_T + (size_t)l*NC*H + (size_t)s*H + h;  // rows s..s+3 = knots s-1..s+2
    float p0=c[0], p1=c[H], p2=c[2*H], p3=c[3*H];
    float bq = p2 - p0;
    float cq = 2.f*p0 - 5.f*p1 + 4.f*p2 - p3;
    float dq = 3.f*(p1 - p2) + p3 - p0;
    float v = 0.5f*(2.f*p1 + t*(bq + t*(cq + t*dq)));
    g_fine[(size_t)l*PFP1*H + idx] = __float2half_rn(v);
}

// ---- aggregation: fp16 fine table linear interp, fp16 x1 gather ----
__global__ void __launch_bounds__(320) agg(int l){
    int i = blockIdx.x, t = threadIdx.x;
    __shared__ int s_j[KM], s_b[KM], s_cnt;
    __shared__ float s_w[KM];
    if(t==0) s_cnt = g_cnt[i];
    if(t<KM){
        int e=i*KM+t;
        s_j[t]=g_nbr[e]*H; s_b[t]=g_base[e]; s_w[t]=g_w1f[e];
    }
    __syncthreads();
    if(t >= 300) return;
    int h = t*2;
    const __half* T = g_fine + (size_t)l*PFP1*H;
    int cnt = s_cnt;
    float ax = 0.f, ay = 0.f;
    #pragma unroll 4
    for(int k=0;k<cnt;k++){
        const __half2* tp = reinterpret_cast<const __half2*>(T + s_b[k] + h);
        float2 t0=__half22float2(__ldg(tp));
        float2 t1=__half22float2(__ldg(tp+300));
        float2 x2=__half22float2(__ldg(reinterpret_cast<const __half2*>(&g_x1h[s_j[k]+h])));
        float w = s_w[k];
        float vx = fmaf(w, t1.x - t0.x, t0.x);
        float vy = fmaf(w, t1.y - t0.y, t0.y);
        ax = fmaf(vx, x2.x, ax);
        ay = fmaf(vy, x2.y, ay);
    }
    float2 o; o.x=ax; o.y=ay;
    *reinterpret_cast<float2*>(&g_msg[i*H+h]) = o;
}

// ---- batched SIMT fp32 GEMM for table build ----
// EPI: 0 plain, 1 ssp, 3 *=extra[m]
template<int EPI>
__global__ void __launch_bounds__(256) sgemm_b(const float* A, const float* B,
        const float* bias, const float* extra, float* Cm,
        int M, int N, int K, long sA, long sB, long sb, long sC){
    int zb = blockIdx.z;
    A  += (size_t)zb * sA;
    B  += (size_t)zb * sB;
    Cm += (size_t)zb * sC;
    if(bias) bias += (size_t)zb * sb;

    const int BM=64, BN=64, BK=16;
    __shared__ float As[BK][BM], Bs[BK][BN];
    int tid=threadIdx.x, tx=tid&15, ty=tid>>4;
    int m0=blockIdx.y*BM, n0=blockIdx.x*BN;
    int ar=tid>>2, ac=(tid&3)<<2, br=tid>>4, bc=(tid&15)<<2;
    float acc[4][4];
    #pragma unroll
    for(int a=0;a<4;a++)
        #pragma unroll
        for(int c=0;c<4;c++) acc[a][c]=0.f;
    for(int k0=0;k0<K;k0+=BK){
        int gm=m0+ar;
        #pragma unroll
        for(int u=0;u<4;u++){
            int gk=k0+ac+u;
            As[ac+u][ar] = (gm<M && gk<K) ? A[(size_t)gm*K+gk] : 0.f;
        }
        int gk2=k0+br;
        #pragma unroll
        for(int u=0;u<4;u++){
            int gn=n0+bc+u;
            Bs[br][bc+u] = (gk2<K && gn<N) ? B[(size_t)gk2*N+gn] : 0.f;
        }
        __syncthreads();
        #pragma unroll
        for(int kk=0;kk<BK;kk++){
            float4 av=*reinterpret_cast<const float4*>(&As[kk][ty<<2]);
            float4 bv=*reinterpret_cast<const float4*>(&Bs[kk][tx<<2]);
            float a0=av.x,a1=av.y,a2=av.z,a3=av.w;
            float b0=bv.x,b1=bv.y,b2=bv.z,b3=bv.w;
            acc[0][0]=fmaf(a0,b0,acc[0][0]); acc[0][1]=fmaf(a0,b1,acc[0][1]);
            acc[0][2]=fmaf(a0,b2,acc[0][2]); acc[0][3]=fmaf(a0,b3,acc[0][3]);
            acc[1][0]=fmaf(a1,b0,acc[1][0]); acc[1][1]=fmaf(a1,b1,acc[1][1]);
            acc[1][2]=fmaf(a1,b2,acc[1][2]); acc[1][3]=fmaf(a1,b3,acc[1][3]);
            acc[2][0]=fmaf(a2,b0,acc[2][0]); acc[2][1]=fmaf(a2,b1,acc[2][1]);
            acc[2][2]=fmaf(a2,b2,acc[2][2]); acc[2][3]=fmaf(a2,b3,acc[2][3]);
            acc[3][0]=fmaf(a3,b0,acc[3][0]); acc[3][1]=fmaf(a3,b1,acc[3][1]);
            acc[3][2]=fmaf(a3,b2,acc[3][2]); acc[3][3]=fmaf(a3,b3,acc[3][3]);
        }
        __syncthreads();
    }
    #pragma unroll
    for(int ii=0;ii<4;ii++){
        int m=m0+(ty<<2)+ii;
        if(m>=M) continue;
        #pragma unroll
        for(int jj=0;jj<4;jj++){
            int n=n0+(tx<<2)+jj;
            if(n>=N) continue;
            float v=acc[ii][jj];
            if(bias) v += bias[n];
            if(EPI==1) v = sspf(v);
            else if(EPI==3) v *= extra[m];
            Cm[(size_t)m*N+n]=v;
        }
    }
}

// ---- node GEMM: fixed M=1024, N=600, K=600; 128x64 tile, 8x8 micro,
//      split-K=6 (100-wide slices), writes partials ----
__global__ void __launch_bounds__(128) sgemm_sk(const float* __restrict__ A,
        const float* __restrict__ B, float* __restrict__ P){
    const int N = H, K = H;
    const int BM=128, BK=16;
    int z = blockIdx.z;
    int kbeg = z * KSLICE;
    int kend = kbeg + KSLICE;
    float* Cm = P + (size_t)z * NN * N;

    __shared__ float As[BK][BM];
    __shared__ float Bs[BK][64];
    int tid = threadIdx.x;
    int tx = tid & 7;            // 8 col groups of 8
    int ty = tid >> 3;           // 16 row groups of 8
    int m0 = blockIdx.y * BM;
    int n0 = blockIdx.x * 64;

    float acc[8][8];
    #pragma unroll
    for(int a=0;a<8;a++)
        #pragma unroll
        for(int c=0;c<8;c++) acc[a][c]=0.f;

    int brow = tid >> 4;         // 0..7
    int bcol = (tid & 15) << 2;  // 0..60

    for(int k0 = kbeg; k0 < kend; k0 += BK){
        {
            const float* ar = A + (size_t)(m0 + tid) * K;
            #pragma unroll
            for(int v=0; v<4; v++){
                int gk = k0 + v*4;
                float4 a4 = (gk < kend) ? *reinterpret_cast<const float4*>(ar + gk)
                                        : make_float4(0.f,0.f,0.f,0.f);
                As[v*4+0][tid] = a4.x;
                As[v*4+1][tid] = a4.y;
                As[v*4+2][tid] = a4.z;
                As[v*4+3][tid] = a4.w;
            }
        }
        #pragma unroll
        for(int s=0; s<2; s++){
            int gk = k0 + brow + s*8;
            int gn = n0 + bcol;
            float4 b4 = (gk < kend && gn < N)
                ? *reinterpret_cast<const float4*>(B + (size_t)gk*N + gn)
                : make_float4(0.f,0.f,0.f,0.f);
            *reinterpret_cast<float4*>(&Bs[brow + s*8][bcol]) = b4;
        }
        __syncthreads();
        #pragma unroll
        for(int kk=0; kk<BK; kk++){
            float a[8], b[8];
            float4 av0 = *reinterpret_cast<const float4*>(&As[kk][ty*8]);
            float4 av1 = *reinterpret_cast<const float4*>(&As[kk][ty*8+4]);
            float4 bv0 = *reinterpret_cast<const float4*>(&Bs[kk][tx*8]);
            float4 bv1 = *reinterpret_cast<const float4*>(&Bs[kk][tx*8+4]);
            a[0]=av0.x;a[1]=av0.y;a[2]=av0.z;a[3]=av0.w;
            a[4]=av1.x;a[5]=av1.y;a[6]=av1.z;a[7]=av1.w;
            b[0]=bv0.x;b[1]=bv0.y;b[2]=bv0.z;b[3]=bv0.w;
            b[4]=bv1.x;b[5]=bv1.y;b[6]=bv1.z;b[7]=bv1.w;
            #pragma unroll
            for(int ii=0;ii<8;ii++)
                #pragma unroll
                for(int jj=0;jj<8;jj++)
                    acc[ii][jj] = fmaf(a[ii], b[jj], acc[ii][jj]);
        }
        __syncthreads();
    }

    #pragma unroll
    for(int ii=0;ii<8;ii++){
        int m = m0 + ty*8 + ii;
        float* cr = Cm + (size_t)m * N;
        #pragma unroll
        for(int jc=0;jc<2;jc++){
            int n = n0 + tx*8 + jc*4;
            if(n < N){
                float4 v;
                v.x = acc[ii][jc*4+0]; v.y = acc[ii][jc*4+1];
                v.z = acc[ii][jc*4+2]; v.w = acc[ii][jc*4+3];
                *reinterpret_cast<float4*>(cr + n) = v;
            }
        }
    }
}

// ---- combine split-K partials + fused epilogue (float4, fixed order) ----
// EPI: 0 write fp16 x1h (no bias), 1 ssp, 2 += extra (residual)
template<int EPI>
__global__ void reduce_epi(const float* __restrict__ bias,
        const float* __restrict__ extra, float* __restrict__ Cm){
    int idx = blockIdx.x*blockDim.x + threadIdx.x;   // float4 index
    if(idx >= NN*H/4) return;
    float4 v = reinterpret_cast<const float4*>(g_part[0])[idx];
    #pragma unroll
    for(int z=1; z<SPLITK; z++){
        const float4 p = reinterpret_cast<const float4*>(g_part[z])[idx];
        v.x += p.x; v.y += p.y; v.z += p.z; v.w += p.w;
    }
    if(bias){
        int n = (idx*4) % H;     // H % 4 == 0
        const float4 bb = *reinterpret_cast<const float4*>(bias + n);
        v.x += bb.x; v.y += bb.y; v.z += bb.z; v.w += bb.w;
    }
    if(EPI==0){
        __half2 h0 = __floats2half2_rn(v.x, v.y);
        __half2 h1 = __floats2half2_rn(v.z, v.w);
        reinterpret_cast<__half2*>(g_x1h)[idx*2]   = h0;
        reinterpret_cast<__half2*>(g_x1h)[idx*2+1] = h1;
        return;
    }
    if(EPI==1){
        v.x = sspf(v.x); v.y = sspf(v.y); v.z = sspf(v.z); v.w = sspf(v.w);
    } else if(EPI==2){
        const float4 e = reinterpret_cast<const float4*>(extra)[idx];
        v.x += e.x; v.y += e.y; v.z += e.z; v.w += e.w;
    }
    reinterpret_cast<float4*>(Cm)[idx] = v;
}

__global__ void pool(){
    int idx = blockIdx.x*blockDim.x + threadIdx.x;
    if(idx >= NB*H) return;
    int b = idx/H, h = idx - b*H;
    const float* p = g_h + (size_t)b*NPG*H + h;
    float s = 0.f;
    #pragma unroll 8
    for(int n=0;n<NPG;n++) s += p[(size_t)n*H];
    g_pool[idx] = s * (1.0f/NPG);
}

__global__ void final_lin(const float* __restrict__ pw, const float* __restrict__ pb,
                          float* __restrict__ out){
    int idx = blockIdx.x*blockDim.x + threadIdx.x;
    if(idx >= NB*H) return;
    int b = idx/H, n = idx - b*H;
    const float* pr = g_pool + b*H;
    float s = pb[n];
    for(int k=0;k<H;k++) s = fmaf(pr[k], pw[(size_t)k*H+n], s);
    out[idx] = s;
}

extern "C" void kernel_launch(void* const* d_in, const int* in_sizes, int n_in,
                              void* d_out, int out_size){
    // dict order: z,pos,emb,w1,b1,w2,b2,lin1,l2w,l2b,ilw,ilb,pw,pb
    int map[14] = {0,1,2,3,4,5,6,7,8,9,10,11,12,13};
    if(!(in_sizes[0]==1024 && in_sizes[1]==3072)){
        int sig[14] = {13,0,1,2,3,4,5,6,7,8,9,10,11,12};
        for(int i=0;i<14;i++) map[i]=sig[i];
    }
    const int*   z    = (const int*)  d_in[map[0]];
    const float* posv = (const float*)d_in[map[1]];
    const float* emb  = (const float*)d_in[map[2]];
    const float* w1   = (const float*)d_in[map[3]];
    const float* b1   = (const float*)d_in[map[4]];
    const float* w2   = (const float*)d_in[map[5]];
    const float* b2   = (const float*)d_in[map[6]];
    const float* lin1 = (const float*)d_in[map[7]];
    const float* l2w  = (const float*)d_in[map[8]];
    const float* l2b  = (const float*)d_in[map[9]];
    const float* ilw  = (const float*)d_in[map[10]];
    const float* ilb  = (const float*)d_in[map[11]];
    const float* pw   = (const float*)d_in[map[12]];
    const float* pb   = (const float*)d_in[map[13]];
    float* out = (float*)d_out;

    float *p_h,*p_msg,*p_m1,*p_T,*p_tmp,*p_ea,*p_C,*p_part;
    cudaGetSymbolAddress((void**)&p_h,   g_h);
    cudaGetSymbolAddress((void**)&p_msg, g_msg);
    cudaGetSymbolAddress((void**)&p_m1,  g_m1);
    cudaGetSymbolAddress((void**)&p_T,   g_T);
    cudaGetSymbolAddress((void**)&p_tmp, g_tmp);
    cudaGetSymbolAddress((void**)&p_ea,  g_ea);
    cudaGetSymbolAddress((void**)&p_C,   g_C);
    cudaGetSymbolAddress((void**)&p_part,g_part);

    build_graph<<<NN, NPG>>>(posv);
    smear<<<(NC*G+255)/256, 256>>>();
    embed<<<(NN*H+255)/256, 256>>>(emb, z);

    // coarse filter tables for all 6 layers (exact fp32), then fine fp16 upsample
    dim3 gT((H+63)/64, (NC+63)/64, NL);
    sgemm_b<1><<<gT,256>>>(p_ea, w1, b1, nullptr, p_tmp,
                           NC, H, G, 0L, (long)G*H, (long)H, (long)NC*H);
    sgemm_b<3><<<gT,256>>>(p_tmp, w2, b2, p_C, p_T,
                           NC, H, H, (long)NC*H, (long)H*H, (long)H, (long)NC*H);
    dim3 gU((PFP1*H+255)/256, NL);
    upsample<<<gU, 256>>>();

    dim3 gSK((H+63)/64, NN/128, SPLITK);   // 10 x 8 x 6 = 480 blocks
    int rblocks = (NN*H/4 + 255)/256;

    for(int l=0;l<NL;l++){
        // x1 = h @ lin1 (no bias) -> fp16
        sgemm_sk<<<gSK,128>>>(p_h, lin1+(size_t)l*H*H, p_part);
        reduce_epi<0><<<rblocks,256>>>(nullptr, nullptr, nullptr);
        agg<<<NN, 320>>>(l);
        // m1 = ssp(msg @ l2w + l2b)
        sgemm_sk<<<gSK,128>>>(p_msg, l2w+(size_t)l*H*H, p_part);
        reduce_epi<1><<<rblocks,256>>>(l2b+(size_t)l*H, nullptr, p_m1);
        // h = h + (m1 @ ilw + ilb)
        sgemm_sk<<<gSK,128>>>(p_m1, ilw+(size_t)l*H*H, p_part);
        reduce_epi<2><<<rblocks,256>>>(ilb+(size_t)l*H, p_h, p_h);
    }
    pool<<<(NB*H+255)/256, 256>>>();
    final_lin<<<(NB*H+255)/256, 256>>>(pw, pb, out);
}